// round 1
// baseline (speedup 1.0000x reference)
#include <cuda_runtime.h>

#define B_    64
#define CIN_  96
#define HW_   784
#define HID_  576
#define NE_   4
#define RED_  24
#define RHID_ 24
#define COUT_ 96
#define EPSBN 1e-3f

// ---- scratch (device globals; no allocation allowed) ----
__device__ float g_rw  [B_ * NE_];
__device__ float g_s   [B_ * HID_];
__device__ float g_sc  [B_ * HID_];
__device__ float g_wpw [B_ * COUT_ * HID_];
__device__ float g_act1[B_ * HID_ * HW_];
__device__ float g_act2[B_ * HID_ * HW_];

__device__ __forceinline__ float sigmoidf_(float v) { return 1.f / (1.f + __expf(-v)); }

// ============================================================
// Kernel 1: routing  (pool -> MLP -> softmax)  grid=64, block=256
// ============================================================
__global__ void k_route(const float* __restrict__ x,
                        const float* __restrict__ w1, const float* __restrict__ b1,
                        const float* __restrict__ w2, const float* __restrict__ b2) {
    int b = blockIdx.x;
    int t = threadIdx.x, lane = t & 31, warp = t >> 5;
    __shared__ float pool[CIN_];
    __shared__ float hdn[RHID_];
    __shared__ float lg[NE_];

    for (int c = warp; c < CIN_; c += 8) {
        const float* xp = x + (b * CIN_ + c) * HW_;
        float s = 0.f;
        for (int i = lane; i < HW_; i += 32) s += xp[i];
        #pragma unroll
        for (int o = 16; o; o >>= 1) s += __shfl_xor_sync(0xffffffffu, s, o);
        if (!lane) pool[c] = s * (1.f / 784.f);
    }
    __syncthreads();
    if (t < RHID_) {
        float a = b1[t];
        for (int c = 0; c < CIN_; c++) a = fmaf(pool[c], w1[t * CIN_ + c], a);
        hdn[t] = fmaxf(a, 0.f);
    }
    __syncthreads();
    if (t < NE_) {
        float a = b2[t];
        for (int j = 0; j < RHID_; j++) a = fmaf(hdn[j], w2[t * RHID_ + j], a);
        lg[t] = a;
    }
    __syncthreads();
    if (t == 0) {
        float mx = fmaxf(fmaxf(lg[0], lg[1]), fmaxf(lg[2], lg[3]));
        float e[4], s = 0.f;
        #pragma unroll
        for (int i = 0; i < 4; i++) { e[i] = __expf(lg[i] - mx); s += e[i]; }
        float inv = 1.f / s;
        #pragma unroll
        for (int i = 0; i < 4; i++) g_rw[b * NE_ + i] = e[i] * inv;
    }
}

// ============================================================
// Kernel 2: expand 1x1 GEMM + BN1 + SiLU
// grid=(14,9,64)  block=128   BM=64 BN=56 K=96 (resident)
// ============================================================
__global__ void k_expand(const float* __restrict__ x, const float* __restrict__ w,
                         const float* __restrict__ gg, const float* __restrict__ bb,
                         const float* __restrict__ mm, const float* __restrict__ vv) {
    __shared__ float ws[CIN_][65];   // padded: conflict-free stores
    __shared__ float xs[CIN_][56];
    int b = blockIdx.z, ot = blockIdx.y, hwt = blockIdx.x;
    int t = threadIdx.x;
    int o0 = ot * 64, hw0 = hwt * 56;

    for (int idx = t; idx < 64 * CIN_; idx += 128) {
        int o = idx / CIN_, c = idx % CIN_;
        ws[c][o] = w[(o0 + o) * CIN_ + c];
    }
    for (int idx = t; idx < CIN_ * 56; idx += 128) {
        int c = idx / 56, n = idx % 56;
        xs[c][n] = x[(b * CIN_ + c) * HW_ + hw0 + n];
    }
    __syncthreads();

    int tx = t & 7, ty = t >> 3;          // tx: 8 (n), ty: 16 (m)
    float acc[4][7] = {};
    for (int k = 0; k < CIN_; k++) {
        float a[4], bv[7];
        #pragma unroll
        for (int i = 0; i < 4; i++) a[i] = ws[k][ty * 4 + i];
        #pragma unroll
        for (int j = 0; j < 7; j++) bv[j] = xs[k][tx * 7 + j];
        #pragma unroll
        for (int i = 0; i < 4; i++)
            #pragma unroll
            for (int j = 0; j < 7; j++) acc[i][j] = fmaf(a[i], bv[j], acc[i][j]);
    }
    #pragma unroll
    for (int i = 0; i < 4; i++) {
        int o = o0 + ty * 4 + i;
        float inv  = gg[o] * rsqrtf(vv[o] + EPSBN);
        float base = bb[o] - mm[o] * inv;
        float* op = g_act1 + (b * HID_ + o) * HW_ + hw0 + tx * 7;
        #pragma unroll
        for (int j = 0; j < 7; j++) {
            float y = fmaf(acc[i][j], inv, base);
            op[j] = y * sigmoidf_(y);
        }
    }
}

// ============================================================
// Kernel 3: MoE depthwise 5x5 + BN2 + SiLU + SE pool
// grid=(576,64)  block=256
// ============================================================
__global__ void k_dw(const float* __restrict__ dw,
                     const float* __restrict__ gg, const float* __restrict__ bb,
                     const float* __restrict__ mm, const float* __restrict__ vv) {
    int c = blockIdx.x, b = blockIdx.y, t = threadIdx.x;
    __shared__ float tile[32 * 32];
    __shared__ float kern[25];
    __shared__ float rwv[NE_];
    __shared__ float red[8];

    if (t < NE_) rwv[t] = g_rw[b * NE_ + t];
    const float* in = g_act1 + (b * HID_ + c) * HW_;
    for (int idx = t; idx < 1024; idx += 256) {
        int r = (idx >> 5) - 2, cc = (idx & 31) - 2;
        tile[idx] = (r >= 0 && r < 28 && cc >= 0 && cc < 28) ? in[r * 28 + cc] : 0.f;
    }
    __syncthreads();
    if (t < 25) {
        float s = 0.f;
        #pragma unroll
        for (int e = 0; e < NE_; e++) s = fmaf(rwv[e], dw[(e * HID_ + c) * 25 + t], s);
        kern[t] = s;
    }
    __syncthreads();

    float inv  = gg[c] * rsqrtf(vv[c] + EPSBN);
    float base = bb[c] - mm[c] * inv;
    float lsum = 0.f;
    float* op = g_act2 + (b * HID_ + c) * HW_;
    for (int p = t; p < HW_; p += 256) {
        int pr = p / 28, pc = p % 28;
        float s = 0.f;
        #pragma unroll
        for (int u = 0; u < 5; u++)
            #pragma unroll
            for (int w2 = 0; w2 < 5; w2++)
                s = fmaf(tile[(pr + u) * 32 + pc + w2], kern[u * 5 + w2], s);
        float y = fmaf(s, inv, base);
        float a = y * sigmoidf_(y);
        op[p] = a;
        lsum += a;
    }
    #pragma unroll
    for (int o = 16; o; o >>= 1) lsum += __shfl_xor_sync(0xffffffffu, lsum, o);
    if ((t & 31) == 0) red[t >> 5] = lsum;
    __syncthreads();
    if (t == 0) {
        float s = 0.f;
        #pragma unroll
        for (int i = 0; i < 8; i++) s += red[i];
        g_s[b * HID_ + c] = s * (1.f / 784.f);
    }
}

// ============================================================
// Kernel 4: SE MLP  grid=64, block=256
// ============================================================
__global__ void k_se(const float* __restrict__ w1, const float* __restrict__ b1,
                     const float* __restrict__ w2, const float* __restrict__ b2) {
    int b = blockIdx.x, t = threadIdx.x;
    __shared__ float sv[HID_];
    __shared__ float zv[RED_];
    for (int i = t; i < HID_; i += 256) sv[i] = g_s[b * HID_ + i];
    __syncthreads();
    if (t < RED_) {
        float a = b1[t];
        for (int c = 0; c < HID_; c++) a = fmaf(sv[c], w1[t * HID_ + c], a);
        zv[t] = a * sigmoidf_(a);
    }
    __syncthreads();
    for (int c = t; c < HID_; c += 256) {
        float a = b2[c];
        #pragma unroll
        for (int j = 0; j < RED_; j++) a = fmaf(zv[j], w2[c * RED_ + j], a);
        g_sc[b * HID_ + c] = sigmoidf_(a);
    }
}

// ============================================================
// Kernel 5: mix pointwise expert weights, fold SE scale
// grid=(12,64)  block=256
// ============================================================
__global__ void k_wpw(const float* __restrict__ pw) {
    int b = blockIdx.y, t = threadIdx.x;
    __shared__ float rwv[NE_];
    if (t < NE_) rwv[t] = g_rw[b * NE_ + t];
    __syncthreads();
    int base = blockIdx.x * 4608;
    for (int idx = base + t; idx < base + 4608; idx += 256) {
        int o = idx / HID_, c = idx % HID_;
        float s = 0.f;
        #pragma unroll
        for (int e = 0; e < NE_; e++) s = fmaf(rwv[e], pw[(e * COUT_ + o) * HID_ + c], s);
        g_wpw[b * COUT_ * HID_ + idx] = s * g_sc[b * HID_ + c];
    }
}

// ============================================================
// Kernel 6: pointwise GEMM + BN3 + residual
// grid=(7,2,64)  block=128   BM=48 BN=112 BK=32  TM=6 TN=7
// ============================================================
__global__ void k_pw(const float* __restrict__ x,
                     const float* __restrict__ gg, const float* __restrict__ bb,
                     const float* __restrict__ mm, const float* __restrict__ vv,
                     float* __restrict__ out) {
    __shared__ float ws[32][49];     // padded
    __shared__ float as[32][112];
    int b = blockIdx.z, ot = blockIdx.y, hwt = blockIdx.x, t = threadIdx.x;
    int o0 = ot * 48, hw0 = hwt * 112;
    int tx = t & 15, ty = t >> 4;     // tx: 16 (n), ty: 8 (m)

    float acc[6][7] = {};
    const float* wp = g_wpw + (b * COUT_ + o0) * HID_;
    const float* ap = g_act2 + b * HID_ * HW_ + hw0;

    for (int k0 = 0; k0 < HID_; k0 += 32) {
        for (int idx = t; idx < 48 * 32; idx += 128) {
            int o = idx >> 5, kk = idx & 31;
            ws[kk][o] = wp[o * HID_ + k0 + kk];
        }
        for (int idx = t; idx < 32 * 112; idx += 128) {
            int kk = idx / 112, n = idx % 112;
            as[kk][n] = ap[(k0 + kk) * HW_ + n];
        }
        __syncthreads();
        for (int kk = 0; kk < 32; kk++) {
            float a[6], bv[7];
            #pragma unroll
            for (int i = 0; i < 6; i++) a[i] = ws[kk][ty * 6 + i];
            #pragma unroll
            for (int j = 0; j < 7; j++) bv[j] = as[kk][tx * 7 + j];
            #pragma unroll
            for (int i = 0; i < 6; i++)
                #pragma unroll
                for (int j = 0; j < 7; j++) acc[i][j] = fmaf(a[i], bv[j], acc[i][j]);
        }
        __syncthreads();
    }
    #pragma unroll
    for (int i = 0; i < 6; i++) {
        int o = o0 + ty * 6 + i;
        float inv  = gg[o] * rsqrtf(vv[o] + EPSBN);
        float base = bb[o] - mm[o] * inv;
        const float* xp = x   + (b * COUT_ + o) * HW_ + hw0 + tx * 7;
        float*       op = out + (b * COUT_ + o) * HW_ + hw0 + tx * 7;
        #pragma unroll
        for (int j = 0; j < 7; j++) op[j] = fmaf(acc[i][j], inv, base) + xp[j];
    }
}

// ============================================================
extern "C" void kernel_launch(void* const* d_in, const int* in_sizes, int n_in,
                              void* d_out, int out_size) {
    const float* x     = (const float*)d_in[0];
    const float* r_w1  = (const float*)d_in[1];
    const float* r_b1  = (const float*)d_in[2];
    const float* r_w2  = (const float*)d_in[3];
    const float* r_b2  = (const float*)d_in[4];
    const float* exp_w = (const float*)d_in[5];
    const float* bn1_g = (const float*)d_in[6];
    const float* bn1_b = (const float*)d_in[7];
    const float* bn1_m = (const float*)d_in[8];
    const float* bn1_v = (const float*)d_in[9];
    const float* dw_w  = (const float*)d_in[10];
    const float* bn2_g = (const float*)d_in[11];
    const float* bn2_b = (const float*)d_in[12];
    const float* bn2_m = (const float*)d_in[13];
    const float* bn2_v = (const float*)d_in[14];
    const float* se_w1 = (const float*)d_in[15];
    const float* se_b1 = (const float*)d_in[16];
    const float* se_w2 = (const float*)d_in[17];
    const float* se_b2 = (const float*)d_in[18];
    const float* pw_w  = (const float*)d_in[19];
    const float* bn3_g = (const float*)d_in[20];
    const float* bn3_b = (const float*)d_in[21];
    const float* bn3_m = (const float*)d_in[22];
    const float* bn3_v = (const float*)d_in[23];
    float* out = (float*)d_out;

    k_route <<<B_, 256>>>(x, r_w1, r_b1, r_w2, r_b2);
    k_expand<<<dim3(14, 9, B_), 128>>>(x, exp_w, bn1_g, bn1_b, bn1_m, bn1_v);
    k_dw    <<<dim3(HID_, B_), 256>>>(dw_w, bn2_g, bn2_b, bn2_m, bn2_v);
    k_se    <<<B_, 256>>>(se_w1, se_b1, se_w2, se_b2);
    k_wpw   <<<dim3(12, B_), 256>>>(pw_w);
    k_pw    <<<dim3(7, 2, B_), 128>>>(x, bn3_g, bn3_b, bn3_m, bn3_v, out);
}

// round 2
// speedup vs baseline: 1.6543x; 1.6543x over previous
#include <cuda_runtime.h>
#include <cstdint>

#define B_    64
#define CIN_  96
#define HW_   784
#define HID_  576
#define NE_   4
#define RED_  24
#define RHID_ 24
#define COUT_ 96
#define EPSBN 1e-3f

// ---- scratch (device globals; no allocation allowed) ----
__device__ float g_rw  [B_ * NE_];
__device__ float g_s   [B_ * HID_];
__device__ float g_wpw [B_ * COUT_ * HID_];
__device__ float g_act1[B_ * HID_ * HW_];
__device__ float g_act2[B_ * HID_ * HW_];

__device__ __forceinline__ float sigmoidf_(float v) { return 1.f / (1.f + __expf(-v)); }

__device__ __forceinline__ uint32_t f2tf32(float f) {
    uint32_t r; asm("cvt.rna.tf32.f32 %0, %1;" : "=r"(r) : "f"(f)); return r;
}

__device__ __forceinline__ void mma_tf32(float* d,
        uint32_t a0, uint32_t a1, uint32_t a2, uint32_t a3,
        uint32_t b0, uint32_t b1) {
    asm volatile(
        "mma.sync.aligned.m16n8k8.row.col.f32.tf32.tf32.f32 "
        "{%0,%1,%2,%3}, {%4,%5,%6,%7}, {%8,%9}, {%0,%1,%2,%3};\n"
        : "+f"(d[0]), "+f"(d[1]), "+f"(d[2]), "+f"(d[3])
        : "r"(a0), "r"(a1), "r"(a2), "r"(a3), "r"(b0), "r"(b1));
}

// ============================================================
// Kernel 1: routing  (pool -> MLP -> softmax)  grid=64, block=256
// ============================================================
__global__ void k_route(const float* __restrict__ x,
                        const float* __restrict__ w1, const float* __restrict__ b1,
                        const float* __restrict__ w2, const float* __restrict__ b2) {
    int b = blockIdx.x;
    int t = threadIdx.x, lane = t & 31, warp = t >> 5;
    __shared__ float pool[CIN_];
    __shared__ float hdn[RHID_];
    __shared__ float lg[NE_];

    for (int c = warp; c < CIN_; c += 8) {
        const float* xp = x + (b * CIN_ + c) * HW_;
        float s = 0.f;
        for (int i = lane; i < HW_; i += 32) s += xp[i];
        #pragma unroll
        for (int o = 16; o; o >>= 1) s += __shfl_xor_sync(0xffffffffu, s, o);
        if (!lane) pool[c] = s * (1.f / 784.f);
    }
    __syncthreads();
    if (t < RHID_) {
        float a = b1[t];
        for (int c = 0; c < CIN_; c++) a = fmaf(pool[c], w1[t * CIN_ + c], a);
        hdn[t] = fmaxf(a, 0.f);
    }
    __syncthreads();
    if (t < NE_) {
        float a = b2[t];
        for (int j = 0; j < RHID_; j++) a = fmaf(hdn[j], w2[t * RHID_ + j], a);
        lg[t] = a;
    }
    __syncthreads();
    if (t == 0) {
        float mx = fmaxf(fmaxf(lg[0], lg[1]), fmaxf(lg[2], lg[3]));
        float e[4], s = 0.f;
        #pragma unroll
        for (int i = 0; i < 4; i++) { e[i] = __expf(lg[i] - mx); s += e[i]; }
        float inv = 1.f / s;
        #pragma unroll
        for (int i = 0; i < 4; i++) g_rw[b * NE_ + i] = e[i] * inv;
    }
}

// ============================================================
// Kernel 2: expand 1x1 GEMM (tf32 mma) + BN1 + SiLU
// grid=(7,9,64)  block=256   BM=64 BN=112 BK=48
// warps: 4 along M (16 rows each) x 2 along N (56 cols each)
// ============================================================
__global__ void k_expand(const float* __restrict__ x, const float* __restrict__ w,
                         const float* __restrict__ gg, const float* __restrict__ bb,
                         const float* __restrict__ mm, const float* __restrict__ vv) {
    __shared__ uint32_t ws[64][52];    // [m][k] stride 52 -> conflict-free frags
    __shared__ uint32_t xs[48][120];   // [k][n] stride 120 -> conflict-free frags
    int b = blockIdx.z, o0 = blockIdx.y * 64, hw0 = blockIdx.x * 112;
    int t = threadIdx.x, lane = t & 31, wid = t >> 5;
    int gid = lane >> 2, tig = lane & 3;
    int wm = wid >> 1, wn = wid & 1;

    float acc[7][4] = {};

    for (int k0 = 0; k0 < CIN_; k0 += 48) {
        for (int i = t; i < 768; i += 256) {          // W: 64 x 48
            int m = i / 12, kq = (i % 12) * 4;
            float4 v = *(const float4*)(w + (o0 + m) * CIN_ + k0 + kq);
            ws[m][kq + 0] = f2tf32(v.x); ws[m][kq + 1] = f2tf32(v.y);
            ws[m][kq + 2] = f2tf32(v.z); ws[m][kq + 3] = f2tf32(v.w);
        }
        for (int i = t; i < 1344; i += 256) {         // X: 48 x 112
            int k = i / 28, nq = (i % 28) * 4;
            float4 v = *(const float4*)(x + (b * CIN_ + k0 + k) * HW_ + hw0 + nq);
            xs[k][nq + 0] = f2tf32(v.x); xs[k][nq + 1] = f2tf32(v.y);
            xs[k][nq + 2] = f2tf32(v.z); xs[k][nq + 3] = f2tf32(v.w);
        }
        __syncthreads();
        #pragma unroll
        for (int ks = 0; ks < 48; ks += 8) {
            int m = wm * 16 + gid;
            uint32_t a0 = ws[m][ks + tig],     a1 = ws[m + 8][ks + tig];
            uint32_t a2 = ws[m][ks + tig + 4], a3 = ws[m + 8][ks + tig + 4];
            #pragma unroll
            for (int ni = 0; ni < 7; ni++) {
                int n = wn * 56 + ni * 8 + gid;
                uint32_t b0 = xs[ks + tig][n], b1 = xs[ks + tig + 4][n];
                mma_tf32(acc[ni], a0, a1, a2, a3, b0, b1);
            }
        }
        __syncthreads();
    }

    int r0 = o0 + wm * 16 + gid;
    int r1 = r0 + 8;
    float inv0 = gg[r0] * rsqrtf(vv[r0] + EPSBN), base0 = bb[r0] - mm[r0] * inv0;
    float inv1 = gg[r1] * rsqrtf(vv[r1] + EPSBN), base1 = bb[r1] - mm[r1] * inv1;
    #pragma unroll
    for (int ni = 0; ni < 7; ni++) {
        int n = hw0 + wn * 56 + ni * 8 + tig * 2;
        float y0 = fmaf(acc[ni][0], inv0, base0);
        float y1 = fmaf(acc[ni][1], inv0, base0);
        float y2 = fmaf(acc[ni][2], inv1, base1);
        float y3 = fmaf(acc[ni][3], inv1, base1);
        float2 v0 = make_float2(y0 * sigmoidf_(y0), y1 * sigmoidf_(y1));
        float2 v1 = make_float2(y2 * sigmoidf_(y2), y3 * sigmoidf_(y3));
        *(float2*)(g_act1 + (size_t)(b * HID_ + r0) * HW_ + n) = v0;
        *(float2*)(g_act1 + (size_t)(b * HID_ + r1) * HW_ + n) = v1;
    }
}

// ============================================================
// Kernel 3: MoE depthwise 5x5 + BN2 + SiLU + SE pool
// grid=(576,64)  block=256
// ============================================================
__global__ void k_dw(const float* __restrict__ dw,
                     const float* __restrict__ gg, const float* __restrict__ bb,
                     const float* __restrict__ mm, const float* __restrict__ vv) {
    int c = blockIdx.x, b = blockIdx.y, t = threadIdx.x;
    __shared__ float tile[32 * 32];
    __shared__ float kern[25];
    __shared__ float rwv[NE_];
    __shared__ float red[8];

    if (t < NE_) rwv[t] = g_rw[b * NE_ + t];
    const float* in = g_act1 + (b * HID_ + c) * HW_;
    for (int idx = t; idx < 1024; idx += 256) {
        int r = (idx >> 5) - 2, cc = (idx & 31) - 2;
        tile[idx] = (r >= 0 && r < 28 && cc >= 0 && cc < 28) ? in[r * 28 + cc] : 0.f;
    }
    __syncthreads();
    if (t < 25) {
        float s = 0.f;
        #pragma unroll
        for (int e = 0; e < NE_; e++) s = fmaf(rwv[e], dw[(e * HID_ + c) * 25 + t], s);
        kern[t] = s;
    }
    __syncthreads();

    float inv  = gg[c] * rsqrtf(vv[c] + EPSBN);
    float base = bb[c] - mm[c] * inv;
    float lsum = 0.f;
    float* op = g_act2 + (b * HID_ + c) * HW_;
    for (int p = t; p < HW_; p += 256) {
        int pr = p / 28, pc = p % 28;
        float s = 0.f;
        #pragma unroll
        for (int u = 0; u < 5; u++)
            #pragma unroll
            for (int w2 = 0; w2 < 5; w2++)
                s = fmaf(tile[(pr + u) * 32 + pc + w2], kern[u * 5 + w2], s);
        float y = fmaf(s, inv, base);
        float a = y * sigmoidf_(y);
        op[p] = a;
        lsum += a;
    }
    #pragma unroll
    for (int o = 16; o; o >>= 1) lsum += __shfl_xor_sync(0xffffffffu, lsum, o);
    if ((t & 31) == 0) red[t >> 5] = lsum;
    __syncthreads();
    if (t == 0) {
        float s = 0.f;
        #pragma unroll
        for (int i = 0; i < 8; i++) s += red[i];
        g_s[b * HID_ + c] = s * (1.f / 784.f);
    }
}

// ============================================================
// Kernel 4: SE MLP (fused) + mix pointwise weights + fold SE scale
// grid=(12,64)  block=256
// ============================================================
__global__ void k_wpw(const float* __restrict__ pw,
                      const float* __restrict__ w1, const float* __restrict__ b1,
                      const float* __restrict__ w2, const float* __restrict__ b2) {
    int b = blockIdx.y, t = threadIdx.x, lane = t & 31, wid = t >> 5;
    __shared__ float rwv[NE_];
    __shared__ float sv[HID_];
    __shared__ float zv[RED_];
    __shared__ float sc[HID_];

    if (t < NE_) rwv[t] = g_rw[b * NE_ + t];
    for (int i = t; i < HID_; i += 256) sv[i] = g_s[b * HID_ + i];
    __syncthreads();

    // z[r] = silu(sv . w1[r] + b1[r])  — one warp per r, 3 r's per warp
    for (int r = wid; r < RED_; r += 8) {
        float s = 0.f;
        for (int c = lane; c < HID_; c += 32) s = fmaf(sv[c], w1[r * HID_ + c], s);
        #pragma unroll
        for (int o = 16; o; o >>= 1) s += __shfl_xor_sync(0xffffffffu, s, o);
        if (!lane) { float a = s + b1[r]; zv[r] = a * sigmoidf_(a); }
    }
    __syncthreads();
    for (int c = t; c < HID_; c += 256) {
        float a = b2[c];
        #pragma unroll
        for (int j = 0; j < RED_; j++) a = fmaf(zv[j], w2[c * RED_ + j], a);
        sc[c] = sigmoidf_(a);
    }
    __syncthreads();

    int base = blockIdx.x * 4608;
    for (int idx = base + t; idx < base + 4608; idx += 256) {
        int o = idx / HID_, c = idx % HID_;
        float s = 0.f;
        #pragma unroll
        for (int e = 0; e < NE_; e++) s = fmaf(rwv[e], pw[(e * COUT_ + o) * HID_ + c], s);
        g_wpw[b * COUT_ * HID_ + idx] = s * sc[c];
    }
}

// ============================================================
// Kernel 5: pointwise GEMM (tf32 mma) + BN3 + residual
// grid=(9,64)  block=256   BM=96(all COUT) BN=96 BK=32
// warps: 2 along M (48 rows) x 4 along N (24 cols)
// ============================================================
__global__ void k_pw(const float* __restrict__ x,
                     const float* __restrict__ gg, const float* __restrict__ bb,
                     const float* __restrict__ mm, const float* __restrict__ vv,
                     float* __restrict__ out) {
    __shared__ uint32_t as_[96][36];   // [o][k] stride 36 -> conflict-free
    __shared__ uint32_t xs[32][104];   // [k][n] stride 104 -> conflict-free
    int b = blockIdx.y, n0 = blockIdx.x * 96;
    int t = threadIdx.x, lane = t & 31, wid = t >> 5;
    int gid = lane >> 2, tig = lane & 3;
    int wm = wid >> 2, wn = wid & 3;

    float acc[3][3][4] = {};
    const float* wp = g_wpw + (size_t)b * COUT_ * HID_;
    const float* ap = g_act2 + (size_t)b * HID_ * HW_;

    for (int k0 = 0; k0 < HID_; k0 += 32) {
        for (int i = t; i < 768; i += 256) {          // W: 96 x 32
            int m = i / 8, kq = (i % 8) * 4;
            float4 v = *(const float4*)(wp + m * HID_ + k0 + kq);
            as_[m][kq + 0] = f2tf32(v.x); as_[m][kq + 1] = f2tf32(v.y);
            as_[m][kq + 2] = f2tf32(v.z); as_[m][kq + 3] = f2tf32(v.w);
        }
        for (int i = t; i < 768; i += 256) {          // act2: 32 x 96 (guarded)
            int k = i / 24, nq = (i % 24) * 4;
            int col = n0 + nq;
            float4 v = make_float4(0.f, 0.f, 0.f, 0.f);
            if (col < HW_) v = *(const float4*)(ap + (k0 + k) * HW_ + col);
            xs[k][nq + 0] = f2tf32(v.x); xs[k][nq + 1] = f2tf32(v.y);
            xs[k][nq + 2] = f2tf32(v.z); xs[k][nq + 3] = f2tf32(v.w);
        }
        __syncthreads();
        #pragma unroll
        for (int ks = 0; ks < 32; ks += 8) {
            uint32_t A[3][4];
            #pragma unroll
            for (int mi = 0; mi < 3; mi++) {
                int m = wm * 48 + mi * 16 + gid;
                A[mi][0] = as_[m][ks + tig];     A[mi][1] = as_[m + 8][ks + tig];
                A[mi][2] = as_[m][ks + tig + 4]; A[mi][3] = as_[m + 8][ks + tig + 4];
            }
            #pragma unroll
            for (int ni = 0; ni < 3; ni++) {
                int n = wn * 24 + ni * 8 + gid;
                uint32_t b0 = xs[ks + tig][n], b1 = xs[ks + tig + 4][n];
                #pragma unroll
                for (int mi = 0; mi < 3; mi++)
                    mma_tf32(acc[mi][ni], A[mi][0], A[mi][1], A[mi][2], A[mi][3], b0, b1);
            }
        }
        __syncthreads();
    }

    #pragma unroll
    for (int mi = 0; mi < 3; mi++) {
        int oA = wm * 48 + mi * 16 + gid;
        int oB = oA + 8;
        float invA = gg[oA] * rsqrtf(vv[oA] + EPSBN), baseA = bb[oA] - mm[oA] * invA;
        float invB = gg[oB] * rsqrtf(vv[oB] + EPSBN), baseB = bb[oB] - mm[oB] * invB;
        #pragma unroll
        for (int ni = 0; ni < 3; ni++) {
            int col = n0 + wn * 24 + ni * 8 + tig * 2;
            if (col < HW_) {
                size_t iA = (size_t)(b * COUT_ + oA) * HW_ + col;
                size_t iB = (size_t)(b * COUT_ + oB) * HW_ + col;
                float2 rA = *(const float2*)(x + iA);
                float2 rB = *(const float2*)(x + iB);
                float2 vA = make_float2(fmaf(acc[mi][ni][0], invA, baseA) + rA.x,
                                        fmaf(acc[mi][ni][1], invA, baseA) + rA.y);
                float2 vB = make_float2(fmaf(acc[mi][ni][2], invB, baseB) + rB.x,
                                        fmaf(acc[mi][ni][3], invB, baseB) + rB.y);
                *(float2*)(out + iA) = vA;
                *(float2*)(out + iB) = vB;
            }
        }
    }
}

// ============================================================
extern "C" void kernel_launch(void* const* d_in, const int* in_sizes, int n_in,
                              void* d_out, int out_size) {
    const float* x     = (const float*)d_in[0];
    const float* r_w1  = (const float*)d_in[1];
    const float* r_b1  = (const float*)d_in[2];
    const float* r_w2  = (const float*)d_in[3];
    const float* r_b2  = (const float*)d_in[4];
    const float* exp_w = (const float*)d_in[5];
    const float* bn1_g = (const float*)d_in[6];
    const float* bn1_b = (const float*)d_in[7];
    const float* bn1_m = (const float*)d_in[8];
    const float* bn1_v = (const float*)d_in[9];
    const float* dw_w  = (const float*)d_in[10];
    const float* bn2_g = (const float*)d_in[11];
    const float* bn2_b = (const float*)d_in[12];
    const float* bn2_m = (const float*)d_in[13];
    const float* bn2_v = (const float*)d_in[14];
    const float* se_w1 = (const float*)d_in[15];
    const float* se_b1 = (const float*)d_in[16];
    const float* se_w2 = (const float*)d_in[17];
    const float* se_b2 = (const float*)d_in[18];
    const float* pw_w  = (const float*)d_in[19];
    const float* bn3_g = (const float*)d_in[20];
    const float* bn3_b = (const float*)d_in[21];
    const float* bn3_m = (const float*)d_in[22];
    const float* bn3_v = (const float*)d_in[23];
    float* out = (float*)d_out;

    k_route <<<B_, 256>>>(x, r_w1, r_b1, r_w2, r_b2);
    k_expand<<<dim3(7, 9, B_), 256>>>(x, exp_w, bn1_g, bn1_b, bn1_m, bn1_v);
    k_dw    <<<dim3(HID_, B_), 256>>>(dw_w, bn2_g, bn2_b, bn2_m, bn2_v);
    k_wpw   <<<dim3(12, B_), 256>>>(pw_w, se_w1, se_b1, se_w2, se_b2);
    k_pw    <<<dim3(9, B_), 256>>>(x, bn3_g, bn3_b, bn3_m, bn3_v, out);
}

// round 3
// speedup vs baseline: 2.9215x; 1.7661x over previous
#include <cuda_runtime.h>
#include <cuda_bf16.h>
#include <cstdint>

#define B_    64
#define CIN_  96
#define HW_   784
#define HID_  576
#define NE_   4
#define RED_  24
#define RHID_ 24
#define COUT_ 96
#define EPSBN 1e-3f

// ---- scratch (device globals) ----
__device__ float    g_rw  [B_ * NE_];
__device__ float    g_s   [B_ * HID_];
__device__ float    g_sc  [B_ * HID_];
__device__ uint32_t g_wpwp[B_ * COUT_ * (HID_ / 2)];          // bf16x2 pairs along c
__device__ uint32_t g_act1p[B_ * HID_ * (HW_ / 2)];           // bf16x2 pairs along hw
__device__ uint32_t g_act2p[B_ * (HID_ / 2) * HW_];           // bf16x2 pairs along channel

__device__ __forceinline__ float sigmoidf_(float v) { return 1.f / (1.f + __expf(-v)); }

__device__ __forceinline__ uint32_t pack2bf(float lo, float hi) {
    uint32_t r; asm("cvt.rn.bf16x2.f32 %0, %1, %2;" : "=r"(r) : "f"(hi), "f"(lo)); return r;
}

__device__ __forceinline__ void mma_bf16(float* d,
        uint32_t a0, uint32_t a1, uint32_t a2, uint32_t a3,
        uint32_t b0, uint32_t b1) {
    asm volatile(
        "mma.sync.aligned.m16n8k16.row.col.f32.bf16.bf16.f32 "
        "{%0,%1,%2,%3}, {%4,%5,%6,%7}, {%8,%9}, {%0,%1,%2,%3};\n"
        : "+f"(d[0]), "+f"(d[1]), "+f"(d[2]), "+f"(d[3])
        : "r"(a0), "r"(a1), "r"(a2), "r"(a3), "r"(b0), "r"(b1));
}

// ============================================================
// Kernel 1: routing  (pool -> MLP -> softmax)  grid=64, block=256
// ============================================================
__global__ void k_route(const float* __restrict__ x,
                        const float* __restrict__ w1, const float* __restrict__ b1,
                        const float* __restrict__ w2, const float* __restrict__ b2) {
    int b = blockIdx.x;
    int t = threadIdx.x, lane = t & 31, warp = t >> 5;
    __shared__ float pool[CIN_];
    __shared__ float hdn[RHID_];
    __shared__ float lg[NE_];

    for (int c = warp; c < CIN_; c += 8) {
        const float* xp = x + (b * CIN_ + c) * HW_;
        float s = 0.f;
        for (int i = lane; i < HW_; i += 32) s += xp[i];
        #pragma unroll
        for (int o = 16; o; o >>= 1) s += __shfl_xor_sync(0xffffffffu, s, o);
        if (!lane) pool[c] = s * (1.f / 784.f);
    }
    __syncthreads();
    if (t < RHID_) {
        float a = b1[t];
        for (int c = 0; c < CIN_; c++) a = fmaf(pool[c], w1[t * CIN_ + c], a);
        hdn[t] = fmaxf(a, 0.f);
    }
    __syncthreads();
    if (t < NE_) {
        float a = b2[t];
        for (int j = 0; j < RHID_; j++) a = fmaf(hdn[j], w2[t * RHID_ + j], a);
        lg[t] = a;
    }
    __syncthreads();
    if (t == 0) {
        float mx = fmaxf(fmaxf(lg[0], lg[1]), fmaxf(lg[2], lg[3]));
        float e[4], s = 0.f;
        #pragma unroll
        for (int i = 0; i < 4; i++) { e[i] = __expf(lg[i] - mx); s += e[i]; }
        float inv = 1.f / s;
        #pragma unroll
        for (int i = 0; i < 4; i++) g_rw[b * NE_ + i] = e[i] * inv;
    }
}

// ============================================================
// Kernel 2: expand 1x1 GEMM (bf16 mma) + BN1 + SiLU -> act1 bf16
// grid=(7,9,64) block=256  BM=64 BN=112 K=96 resident
// warps: 4 along M x 2 along N
// ============================================================
__global__ void k_expand(const float* __restrict__ x, const float* __restrict__ w,
                         const float* __restrict__ gg, const float* __restrict__ bb,
                         const float* __restrict__ mm, const float* __restrict__ vv) {
    __shared__ uint32_t ws[64][50];    // [m][kpair] K=96 -> 48 pairs (+2 pad)
    __shared__ uint32_t xs[48][120];   // [kpair][n] n=112 (+8 pad)
    int b = blockIdx.z, o0 = blockIdx.y * 64, hw0 = blockIdx.x * 112;
    int t = threadIdx.x, lane = t & 31, wid = t >> 5;
    int gid = lane >> 2, tig = lane & 3;
    int wm = wid >> 1, wn = wid & 1;

    for (int i = t; i < 1536; i += 256) {            // W: 64 x 96 (24 float4/row)
        int m = i / 24, q = i % 24;
        float4 v = *(const float4*)(w + (o0 + m) * CIN_ + 4 * q);
        ws[m][2 * q]     = pack2bf(v.x, v.y);
        ws[m][2 * q + 1] = pack2bf(v.z, v.w);
    }
    for (int i = t; i < 1344; i += 256) {            // X: 48 kpairs x 112 (28 float4)
        int kp = i / 28, q = i % 28;
        const float* p0 = x + (b * CIN_ + 2 * kp) * HW_ + hw0 + 4 * q;
        float4 v0 = *(const float4*)p0;
        float4 v1 = *(const float4*)(p0 + HW_);
        xs[kp][4 * q + 0] = pack2bf(v0.x, v1.x);
        xs[kp][4 * q + 1] = pack2bf(v0.y, v1.y);
        xs[kp][4 * q + 2] = pack2bf(v0.z, v1.z);
        xs[kp][4 * q + 3] = pack2bf(v0.w, v1.w);
    }
    __syncthreads();

    float acc[7][4] = {};
    #pragma unroll
    for (int s = 0; s < 6; s++) {
        int m = wm * 16 + gid;
        int kp = s * 8 + tig;
        uint32_t a0 = ws[m][kp],     a1 = ws[m + 8][kp];
        uint32_t a2 = ws[m][kp + 4], a3 = ws[m + 8][kp + 4];
        #pragma unroll
        for (int ni = 0; ni < 7; ni++) {
            int n = wn * 56 + ni * 8 + gid;
            mma_bf16(acc[ni], a0, a1, a2, a3, xs[kp][n], xs[kp + 4][n]);
        }
    }

    int r0 = o0 + wm * 16 + gid;
    int r1 = r0 + 8;
    float inv0 = gg[r0] * rsqrtf(vv[r0] + EPSBN), base0 = bb[r0] - mm[r0] * inv0;
    float inv1 = gg[r1] * rsqrtf(vv[r1] + EPSBN), base1 = bb[r1] - mm[r1] * inv1;
    #pragma unroll
    for (int ni = 0; ni < 7; ni++) {
        int n = hw0 + wn * 56 + ni * 8 + tig * 2;
        float y0 = fmaf(acc[ni][0], inv0, base0);
        float y1 = fmaf(acc[ni][1], inv0, base0);
        float y2 = fmaf(acc[ni][2], inv1, base1);
        float y3 = fmaf(acc[ni][3], inv1, base1);
        g_act1p[(b * HID_ + r0) * (HW_ / 2) + n / 2] = pack2bf(y0 * sigmoidf_(y0), y1 * sigmoidf_(y1));
        g_act1p[(b * HID_ + r1) * (HW_ / 2) + n / 2] = pack2bf(y2 * sigmoidf_(y2), y3 * sigmoidf_(y3));
    }
}

// ============================================================
// Kernel 3: MoE depthwise 5x5 + BN2 + SiLU + SE pool
// grid=(288,64) block=256 — one block per (batch, channel-pair)
// thread computes a 4-wide patch for BOTH channels, packs bf16x2
// ============================================================
__global__ void k_dw(const float* __restrict__ dw,
                     const float* __restrict__ gg, const float* __restrict__ bb,
                     const float* __restrict__ mm, const float* __restrict__ vv) {
    int cp = blockIdx.x, b = blockIdx.y, t = threadIdx.x;
    int ch0 = 2 * cp, ch1 = ch0 + 1;
    __shared__ float t0[1024], t1[1024];
    __shared__ float k0s[25], k1s[25];
    __shared__ float rwv[NE_];
    __shared__ float red[8][2];

    if (t < NE_) rwv[t] = g_rw[b * NE_ + t];
    const __nv_bfloat16* a1 = (const __nv_bfloat16*)g_act1p;
    const __nv_bfloat16* in0 = a1 + (size_t)(b * HID_ + ch0) * HW_;
    const __nv_bfloat16* in1 = in0 + HW_;
    for (int idx = t; idx < 1024; idx += 256) {
        int r = (idx >> 5) - 2, cc = (idx & 31) - 2;
        bool ok = (r >= 0 && r < 28 && cc >= 0 && cc < 28);
        t0[idx] = ok ? __bfloat162float(in0[r * 28 + cc]) : 0.f;
        t1[idx] = ok ? __bfloat162float(in1[r * 28 + cc]) : 0.f;
    }
    __syncthreads();
    if (t < 50) {
        int kk = t % 25;
        int ch = (t < 25) ? ch0 : ch1;
        float s = 0.f;
        #pragma unroll
        for (int e = 0; e < NE_; e++) s = fmaf(rwv[e], dw[(e * HID_ + ch) * 25 + kk], s);
        ((t < 25) ? k0s : k1s)[kk] = s;
    }
    __syncthreads();

    float lsum0 = 0.f, lsum1 = 0.f;
    if (t < 196) {
        int row = t / 7, cb = (t % 7) * 4;
        float o0[4] = {}, o1[4] = {};
        {
            float kr[25];
            #pragma unroll
            for (int i = 0; i < 25; i++) kr[i] = k0s[i];
            float win[5][8];
            #pragma unroll
            for (int u = 0; u < 5; u++)
                #pragma unroll
                for (int wj = 0; wj < 8; wj++) win[u][wj] = t0[(row + u) * 32 + cb + wj];
            #pragma unroll
            for (int j = 0; j < 4; j++)
                #pragma unroll
                for (int u = 0; u < 5; u++)
                    #pragma unroll
                    for (int w2 = 0; w2 < 5; w2++)
                        o0[j] = fmaf(win[u][w2 + j], kr[u * 5 + w2], o0[j]);
        }
        {
            float kr[25];
            #pragma unroll
            for (int i = 0; i < 25; i++) kr[i] = k1s[i];
            float win[5][8];
            #pragma unroll
            for (int u = 0; u < 5; u++)
                #pragma unroll
                for (int wj = 0; wj < 8; wj++) win[u][wj] = t1[(row + u) * 32 + cb + wj];
            #pragma unroll
            for (int j = 0; j < 4; j++)
                #pragma unroll
                for (int u = 0; u < 5; u++)
                    #pragma unroll
                    for (int w2 = 0; w2 < 5; w2++)
                        o1[j] = fmaf(win[u][w2 + j], kr[u * 5 + w2], o1[j]);
        }
        float inv0 = gg[ch0] * rsqrtf(vv[ch0] + EPSBN), base0 = bb[ch0] - mm[ch0] * inv0;
        float inv1 = gg[ch1] * rsqrtf(vv[ch1] + EPSBN), base1 = bb[ch1] - mm[ch1] * inv1;
        uint32_t pk[4];
        #pragma unroll
        for (int j = 0; j < 4; j++) {
            float y0 = fmaf(o0[j], inv0, base0); float a0v = y0 * sigmoidf_(y0);
            float y1 = fmaf(o1[j], inv1, base1); float a1v = y1 * sigmoidf_(y1);
            lsum0 += a0v; lsum1 += a1v;
            pk[j] = pack2bf(a0v, a1v);
        }
        *(uint4*)(g_act2p + (size_t)(b * (HID_ / 2) + cp) * HW_ + row * 28 + cb) =
            make_uint4(pk[0], pk[1], pk[2], pk[3]);
    }
    #pragma unroll
    for (int o = 16; o; o >>= 1) {
        lsum0 += __shfl_xor_sync(0xffffffffu, lsum0, o);
        lsum1 += __shfl_xor_sync(0xffffffffu, lsum1, o);
    }
    if ((t & 31) == 0) { red[t >> 5][0] = lsum0; red[t >> 5][1] = lsum1; }
    __syncthreads();
    if (t == 0) {
        float s0 = 0.f, s1 = 0.f;
        #pragma unroll
        for (int i = 0; i < 8; i++) { s0 += red[i][0]; s1 += red[i][1]; }
        g_s[b * HID_ + ch0] = s0 * (1.f / 784.f);
        g_s[b * HID_ + ch1] = s1 * (1.f / 784.f);
    }
}

// ============================================================
// Kernel 4: SE MLP -> g_sc   grid=64, block=256
// ============================================================
__global__ void k_se(const float* __restrict__ w1, const float* __restrict__ b1,
                     const float* __restrict__ w2, const float* __restrict__ b2) {
    int b = blockIdx.x, t = threadIdx.x, lane = t & 31, wid = t >> 5;
    __shared__ float sv[HID_];
    __shared__ float zv[RED_];
    for (int i = t; i < HID_; i += 256) sv[i] = g_s[b * HID_ + i];
    __syncthreads();
    for (int r = wid; r < RED_; r += 8) {
        float s = 0.f;
        for (int c = lane; c < HID_; c += 32) s = fmaf(sv[c], w1[r * HID_ + c], s);
        #pragma unroll
        for (int o = 16; o; o >>= 1) s += __shfl_xor_sync(0xffffffffu, s, o);
        if (!lane) { float a = s + b1[r]; zv[r] = a * sigmoidf_(a); }
    }
    __syncthreads();
    for (int c = t; c < HID_; c += 256) {
        float a = b2[c];
        #pragma unroll
        for (int j = 0; j < RED_; j++) a = fmaf(zv[j], w2[c * RED_ + j], a);
        g_sc[b * HID_ + c] = sigmoidf_(a);
    }
}

// ============================================================
// Kernel 5: mix pointwise weights + fold SE scale -> bf16 pairs
// grid=(9,12) block=256 (8 o x 32 cpair); loops all 64 batches
// pw_w is read exactly ONCE from DRAM.
// ============================================================
__global__ void k_wpw(const float* __restrict__ pw) {
    int t = threadIdx.x, lane = t & 31, ty = t >> 5;
    int o = blockIdx.y * 8 + ty;
    int cp = blockIdx.x * 32 + lane;
    __shared__ float rws[B_][NE_];
    __shared__ float scs[B_][64];

    for (int i = t; i < B_ * NE_; i += 256) rws[i >> 2][i & 3] = g_rw[i];
    for (int i = t; i < B_ * 64; i += 256) {
        int bb2 = i / 64, j = i % 64;
        scs[bb2][j] = g_sc[bb2 * HID_ + blockIdx.x * 64 + j];
    }
    __syncthreads();

    float p0[NE_], p1[NE_];
    #pragma unroll
    for (int e = 0; e < NE_; e++) {
        float2 v = *(const float2*)(pw + (size_t)(e * COUT_ + o) * HID_ + 2 * cp);
        p0[e] = v.x; p1[e] = v.y;
    }
    int jl = lane * 2;
    for (int b = 0; b < B_; b++) {
        float w0 = 0.f, w1 = 0.f;
        #pragma unroll
        for (int e = 0; e < NE_; e++) {
            w0 = fmaf(rws[b][e], p0[e], w0);
            w1 = fmaf(rws[b][e], p1[e], w1);
        }
        g_wpwp[(size_t)(b * COUT_ + o) * (HID_ / 2) + cp] =
            pack2bf(w0 * scs[b][jl], w1 * scs[b][jl + 1]);
    }
}

// ============================================================
// Kernel 6: pointwise GEMM (bf16 mma) + BN3 + residual
// grid=(9,64) block=256  BM=96 BN=96 BK=64 (32 pairs)
// warps: 2 along M x 4 along N
// ============================================================
__global__ void k_pw(const float* __restrict__ x,
                     const float* __restrict__ gg, const float* __restrict__ bb,
                     const float* __restrict__ mm, const float* __restrict__ vv,
                     float* __restrict__ out) {
    __shared__ uint32_t ws[96][36];    // [o][kpair]  stride 36 -> conflict-free
    __shared__ uint32_t xs[32][104];   // [kpair][n]  stride 104 -> conflict-free
    int b = blockIdx.y, n0 = blockIdx.x * 96;
    int t = threadIdx.x, lane = t & 31, wid = t >> 5;
    int gid = lane >> 2, tig = lane & 3;
    int wm = wid >> 2, wn = wid & 3;

    float acc[3][3][4] = {};
    const uint32_t* wp = g_wpwp + (size_t)b * COUT_ * (HID_ / 2);
    const uint32_t* ap = g_act2p + (size_t)b * (HID_ / 2) * HW_;

    for (int k0p = 0; k0p < HID_ / 2; k0p += 32) {
        for (int i = t; i < 3072; i += 256) {
            int m = i >> 5, kp = i & 31;
            ws[m][kp] = wp[m * (HID_ / 2) + k0p + kp];
        }
        for (int i = t; i < 3072; i += 256) {
            int kp = i / 96, n = i % 96;
            int col = n0 + n;
            xs[kp][n] = (col < HW_) ? ap[(k0p + kp) * HW_ + col] : 0u;
        }
        __syncthreads();
        #pragma unroll
        for (int s = 0; s < 4; s++) {
            int kp = s * 8 + tig;
            uint32_t A[3][4];
            #pragma unroll
            for (int mi = 0; mi < 3; mi++) {
                int m = wm * 48 + mi * 16 + gid;
                A[mi][0] = ws[m][kp];     A[mi][1] = ws[m + 8][kp];
                A[mi][2] = ws[m][kp + 4]; A[mi][3] = ws[m + 8][kp + 4];
            }
            #pragma unroll
            for (int ni = 0; ni < 3; ni++) {
                int n = wn * 24 + ni * 8 + gid;
                uint32_t b0 = xs[kp][n], b1 = xs[kp + 4][n];
                #pragma unroll
                for (int mi = 0; mi < 3; mi++)
                    mma_bf16(acc[mi][ni], A[mi][0], A[mi][1], A[mi][2], A[mi][3], b0, b1);
            }
        }
        __syncthreads();
    }

    #pragma unroll
    for (int mi = 0; mi < 3; mi++) {
        int oA = wm * 48 + mi * 16 + gid;
        int oB = oA + 8;
        float invA = gg[oA] * rsqrtf(vv[oA] + EPSBN), baseA = bb[oA] - mm[oA] * invA;
        float invB = gg[oB] * rsqrtf(vv[oB] + EPSBN), baseB = bb[oB] - mm[oB] * invB;
        #pragma unroll
        for (int ni = 0; ni < 3; ni++) {
            int col = n0 + wn * 24 + ni * 8 + tig * 2;
            if (col < HW_) {
                size_t iA = (size_t)(b * COUT_ + oA) * HW_ + col;
                size_t iB = (size_t)(b * COUT_ + oB) * HW_ + col;
                float2 rA = *(const float2*)(x + iA);
                float2 rB = *(const float2*)(x + iB);
                *(float2*)(out + iA) = make_float2(fmaf(acc[mi][ni][0], invA, baseA) + rA.x,
                                                   fmaf(acc[mi][ni][1], invA, baseA) + rA.y);
                *(float2*)(out + iB) = make_float2(fmaf(acc[mi][ni][2], invB, baseB) + rB.x,
                                                   fmaf(acc[mi][ni][3], invB, baseB) + rB.y);
            }
        }
    }
}

// ============================================================
extern "C" void kernel_launch(void* const* d_in, const int* in_sizes, int n_in,
                              void* d_out, int out_size) {
    const float* x     = (const float*)d_in[0];
    const float* r_w1  = (const float*)d_in[1];
    const float* r_b1  = (const float*)d_in[2];
    const float* r_w2  = (const float*)d_in[3];
    const float* r_b2  = (const float*)d_in[4];
    const float* exp_w = (const float*)d_in[5];
    const float* bn1_g = (const float*)d_in[6];
    const float* bn1_b = (const float*)d_in[7];
    const float* bn1_m = (const float*)d_in[8];
    const float* bn1_v = (const float*)d_in[9];
    const float* dw_w  = (const float*)d_in[10];
    const float* bn2_g = (const float*)d_in[11];
    const float* bn2_b = (const float*)d_in[12];
    const float* bn2_m = (const float*)d_in[13];
    const float* bn2_v = (const float*)d_in[14];
    const float* se_w1 = (const float*)d_in[15];
    const float* se_b1 = (const float*)d_in[16];
    const float* se_w2 = (const float*)d_in[17];
    const float* se_b2 = (const float*)d_in[18];
    const float* pw_w  = (const float*)d_in[19];
    const float* bn3_g = (const float*)d_in[20];
    const float* bn3_b = (const float*)d_in[21];
    const float* bn3_m = (const float*)d_in[22];
    const float* bn3_v = (const float*)d_in[23];
    float* out = (float*)d_out;

    k_route <<<B_, 256>>>(x, r_w1, r_b1, r_w2, r_b2);
    k_expand<<<dim3(7, 9, B_), 256>>>(x, exp_w, bn1_g, bn1_b, bn1_m, bn1_v);
    k_dw    <<<dim3(HID_ / 2, B_), 256>>>(dw_w, bn2_g, bn2_b, bn2_m, bn2_v);
    k_se    <<<B_, 256>>>(se_w1, se_b1, se_w2, se_b2);
    k_wpw   <<<dim3(9, 12), 256>>>(pw_w);
    k_pw    <<<dim3(9, B_), 256>>>(x, bn3_g, bn3_b, bn3_m, bn3_v, out);
}